// round 11
// baseline (speedup 1.0000x reference)
#include <cuda_runtime.h>

// Problem constants
#define BB     32
#define HQ     32
#define HKV    8
#define DD     128
#define SS     4096
#define GG     4          // HQ / HKV
#define NWARP  4
#define NTHR   128
#define SLOTS  (NWARP * 2)   // 8 tokens per CTA iteration (2 per warp: 16-lane groups)
#define NCTA   592           // 148 SMs x 4 resident CTAs -> exactly one wave

// Final accumulators (same layout as out) + normalizers
__device__ float g_acc[(size_t)BB * HQ * DD];   // 2 MB
__device__ float g_l[BB * HQ];

__device__ __forceinline__ float dot4(float4 a, float4 b) {
    return a.x*b.x + a.y*b.y + a.z*b.z + a.w*b.w;
}

__global__ void zero_scratch()
{
    const int n = BB * HQ * DD;
    for (int i = blockIdx.x * blockDim.x + threadIdx.x; i < n; i += gridDim.x * blockDim.x)
        g_acc[i] = 0.f;
    if (blockIdx.x == 0)
        for (int i = threadIdx.x; i < BB * HQ; i += blockDim.x) g_l[i] = 0.f;
}

__global__ __launch_bounds__(NTHR, 4) void attn_persistent(
    const float* __restrict__ xq, const float* __restrict__ xk,
    const float* __restrict__ xv, const float* __restrict__ kv,
    const int* __restrict__ cur_sel, const int* __restrict__ table,
    const int* __restrict__ seqlens)
{
    const int tid  = threadIdx.x;
    const int wid  = tid >> 5;
    const int lane = tid & 31;
    const int sub  = lane & 15;          // position within 16-lane group
    const int grp  = lane >> 4;          // which token this half-warp owns
    const int myslot = wid * 2 + grp;    // 0..7 token slot per CTA iteration

    // 16B-aligned: sh_acc is accessed via float4 (STS.128 needs 16B alignment)
    __shared__ __align__(16) float sh_acc[NWARP][GG][DD];   // 8 KB
    __shared__ __align__(16) float sh_l[NWARP][GG];
    __shared__ int pre[BB + 4];          // prefix sums of seq_len (padded)

    // prefix scan of the 32 seq_lens (warp 0)
    if (tid < 32) {
        int v = seqlens[tid];
#pragma unroll
        for (int off = 1; off < 32; off <<= 1) {
            int o = __shfl_up_sync(0xffffffffu, v, off);
            if (lane >= off) v += o;
        }
        pre[tid + 1] = v;
        if (tid == 0) pre[0] = 0;
    }
    __syncthreads();

    const int  total = pre[BB];
    const long Wtot  = (long)HKV * total;
    long idx       = (long)blockIdx.x * Wtot / NCTA;
    const long hiW = (long)(blockIdx.x + 1) * Wtot / NCTA;

    const float scale = 0.08838834764831845f * 1.4426950408889634f;
    const size_t rowsz = (size_t)(2 * HKV * DD);

    while (idx < hiW) {
        // map global index -> (h, b, s0); run = contiguous tokens of one (b,h)
        const int h   = (int)(idx / total);
        const int rem = (int)(idx - (long)h * total);
        int b = 0;
        while (pre[b + 1] <= rem) b++;
        const int s0 = rem - pre[b];
        long run_end = (long)h * total + pre[b + 1];
        if (run_end > hiW) run_end = hiW;
        const int n = (int)(run_end - idx);

        const int    cur   = cur_sel[b];
        const int    tbase = b * SS;
        const size_t qkvo  = ((size_t)b * HKV + h) * DD;
        const size_t koff  = (size_t)h * DD;
        const size_t voff  = (size_t)(HKV + h) * DD;

        // load Q for this (b,h): lane owns dims {c*64 + sub*4 ..+3}
        float4 qv[GG][2];
#pragma unroll
        for (int g = 0; g < GG; g++)
#pragma unroll
            for (int c = 0; c < 2; c++) {
                float4 q = *(const float4*)(xq + ((size_t)b * HQ + h * GG + g) * DD
                                            + c * 64 + sub * 4);
                q.x *= scale; q.y *= scale; q.z *= scale; q.w *= scale;
                qv[g][c] = q;
            }

        float  l[GG];
        float4 acc[GG][2];
#pragma unroll
        for (int g = 0; g < GG; g++) {
            l[g] = 0.f;
            acc[g][0] = make_float4(0.f,0.f,0.f,0.f);
            acc[g][1] = make_float4(0.f,0.f,0.f,0.f);
        }

        const int smax  = s0 + n - 1;
        const int niter = (n + SLOTS - 1) / SLOTS;

        // depth-2 rotated prefetch
        float4 bk[2][2], bv[2][2];
        int    nr[2];
#pragma unroll
        for (int st = 0; st < 2; st++) {
            int s = min(s0 + st * SLOTS + myslot, smax);
            int r = __ldg(table + tbase + s);
            const float* kp = (r == cur) ? xk + qkvo : kv + (size_t)r * rowsz + koff;
            const float* vp = (r == cur) ? xv + qkvo : kv + (size_t)r * rowsz + voff;
            bk[st][0] = *(const float4*)(kp + sub * 4);
            bk[st][1] = *(const float4*)(kp + sub * 4 + 64);
            bv[st][0] = *(const float4*)(vp + sub * 4);
            bv[st][1] = *(const float4*)(vp + sub * 4 + 64);
        }
#pragma unroll
        for (int st = 0; st < 2; st++)
            nr[st] = __ldg(table + tbase + min(s0 + (2 + st) * SLOTS + myslot, smax));

        for (int i = 0; i < niter; i += 2) {
#pragma unroll
            for (int st = 0; st < 2; st++) {
                const int it = i + st;
                if (st == 1 && it >= niter) break;

                float4 k0 = bk[st][0], k1 = bk[st][1];
                float4 v0 = bv[st][0], v1 = bv[st][1];

                // refill stage with iteration (it+2)
                {
                    int r = nr[st];
                    const float* kp = (r == cur) ? xk + qkvo : kv + (size_t)r * rowsz + koff;
                    const float* vp = (r == cur) ? xv + qkvo : kv + (size_t)r * rowsz + voff;
                    bk[st][0] = *(const float4*)(kp + sub * 4);
                    bk[st][1] = *(const float4*)(kp + sub * 4 + 64);
                    bv[st][0] = *(const float4*)(vp + sub * 4);
                    bv[st][1] = *(const float4*)(vp + sub * 4 + 64);
                    nr[st] = __ldg(table + tbase
                                   + min(s0 + (it + 4) * SLOTS + myslot, smax));
                }

                float x[GG];
#pragma unroll
                for (int g = 0; g < GG; g++)
                    x[g] = dot4(k0, qv[g][0]) + dot4(k1, qv[g][1]);

#pragma unroll
                for (int g = 0; g < GG; g++) x[g] += __shfl_xor_sync(0xffffffffu, x[g], 1);
#pragma unroll
                for (int g = 0; g < GG; g++) x[g] += __shfl_xor_sync(0xffffffffu, x[g], 2);
#pragma unroll
                for (int g = 0; g < GG; g++) x[g] += __shfl_xor_sync(0xffffffffu, x[g], 4);
#pragma unroll
                for (int g = 0; g < GG; g++) x[g] += __shfl_xor_sync(0xffffffffu, x[g], 8);

                const bool valid = (it * SLOTS + myslot) < n;
#pragma unroll
                for (int g = 0; g < GG; g++) {
                    float p = valid ? exp2f(x[g]) : 0.f;
                    l[g] += p;
                    acc[g][0].x += p * v0.x; acc[g][0].y += p * v0.y;
                    acc[g][0].z += p * v0.z; acc[g][0].w += p * v0.w;
                    acc[g][1].x += p * v1.x; acc[g][1].y += p * v1.y;
                    acc[g][1].z += p * v1.z; acc[g][1].w += p * v1.w;
                }
            }
        }

        // merge the two 16-lane groups: xor 16
#pragma unroll
        for (int g = 0; g < GG; g++) {
#pragma unroll
            for (int c = 0; c < 2; c++) {
                acc[g][c].x += __shfl_xor_sync(0xffffffffu, acc[g][c].x, 16);
                acc[g][c].y += __shfl_xor_sync(0xffffffffu, acc[g][c].y, 16);
                acc[g][c].z += __shfl_xor_sync(0xffffffffu, acc[g][c].z, 16);
                acc[g][c].w += __shfl_xor_sync(0xffffffffu, acc[g][c].w, 16);
            }
            l[g] += __shfl_xor_sync(0xffffffffu, l[g], 16);
        }

        if (grp == 0) {
#pragma unroll
            for (int g = 0; g < GG; g++) {
#pragma unroll
                for (int c = 0; c < 2; c++)
                    *(float4*)&sh_acc[wid][g][c * 64 + sub * 4] = acc[g][c];
                if (sub == 0) sh_l[wid][g] = l[g];
            }
        }
        __syncthreads();

        // cross-warp merge + atomic flush into final accumulator
        for (int i2 = tid; i2 < GG * DD; i2 += NTHR) {
            const int g = i2 >> 7;
            const int d = i2 & (DD - 1);
            float A = 0.f;
#pragma unroll
            for (int w = 0; w < NWARP; w++) A += sh_acc[w][g][d];
            atomicAdd(&g_acc[((size_t)b * HQ + h * GG + g) * DD + d], A);
            if (d == 0) {
                float L = 0.f;
#pragma unroll
                for (int w = 0; w < NWARP; w++) L += sh_l[w][g];
                atomicAdd(&g_l[b * HQ + h * GG + g], L);
            }
        }
        __syncthreads();   // smem reuse guard for next run

        idx = run_end;
    }
}

__global__ __launch_bounds__(DD) void attn_finalize(float* __restrict__ out)
{
    const int bq = blockIdx.x;
    const int d  = threadIdx.x;
    out[(size_t)bq * DD + d] = g_acc[(size_t)bq * DD + d] / g_l[bq];
}

extern "C" void kernel_launch(void* const* d_in, const int* in_sizes, int n_in,
                              void* d_out, int out_size)
{
    const float* xq      = (const float*)d_in[0];
    const float* xk      = (const float*)d_in[1];
    const float* xv      = (const float*)d_in[2];
    const float* kv      = (const float*)d_in[3];
    const int*   cur_sel = (const int*)d_in[4];
    const int*   table   = (const int*)d_in[5];
    const int*   seqlens = (const int*)d_in[6];
    float*       out     = (float*)d_out;

    zero_scratch<<<256, 256>>>();
    attn_persistent<<<NCTA, NTHR>>>(xq, xk, xv, kv, cur_sel, table, seqlens);
    attn_finalize<<<BB * HQ, DD>>>(out);
}

// round 14
// speedup vs baseline: 1.1009x; 1.1009x over previous
#include <cuda_runtime.h>

// Problem constants
#define BB     32
#define HQ     32
#define HKV    8
#define DD     128
#define SS     4096
#define GG     4          // HQ / HKV
#define NSPLIT 16         // interleaved: split i takes tokens s ≡ i (mod 16)
#define NWARP  4
#define NTHR   128
#define SLOTS  (NWARP * 2)   // 8 tokens per CTA iteration (2 per warp: 16-lane groups)

// Split-KV partial scratch (allocation-free: __device__ globals)
__device__ float g_pacc[(size_t)NSPLIT * BB * HQ * DD];   // 8.4 MB
__device__ float g_pl[NSPLIT * BB * HQ];
__device__ int   g_perm[BB];     // batches sorted by descending seq_len (LPT)

__device__ __forceinline__ float dot4(float4 a, float4 b) {
    return a.x*b.x + a.y*b.y + a.z*b.z + a.w*b.w;
}

// LPT schedule: rank batches by descending seq_len so the longest-running CTAs
// (blockIdx.z small) launch in the first waves; the final wave holds the
// shortest CTAs -> minimal straggler tail. O(32^2), one warp.
__global__ void sort_batches(const int* __restrict__ seqlens)
{
    const int b = threadIdx.x;
    const int len = seqlens[b];
    int rank = 0;
    for (int j = 0; j < BB; j++) {
        int lj = seqlens[j];
        if (lj > len || (lj == len && j < b)) rank++;
    }
    g_perm[rank] = b;
}

__global__ __launch_bounds__(NTHR, 4) void attn_partial(
    const float* __restrict__ xq, const float* __restrict__ xk,
    const float* __restrict__ xv, const float* __restrict__ kv,
    const int* __restrict__ cur_sel, const int* __restrict__ table,
    const int* __restrict__ seqlens)
{
    const int split = blockIdx.x;
    const int h     = blockIdx.y;
    const int b     = g_perm[blockIdx.z];   // LPT: longest batches first

    const int seq_len = seqlens[b];
    // Interleaved split: tokens s = split + NSPLIT * t, t in [0, nt).
    // seq_len >= 1024 > NSPLIT, so nt >= 64: every split is always active.
    const int nt  = (seq_len - split + NSPLIT - 1) / NSPLIT;
    const int cur = cur_sel[b];

    const int tid  = threadIdx.x;
    const int wid  = tid >> 5;
    const int lane = tid & 31;
    const int sub  = lane & 15;          // position within 16-lane group
    const int grp  = lane >> 4;          // 0 or 1: which token this half-warp owns
    const int myslot = wid * 2 + grp;    // 0..7 token slot within CTA iteration

    __shared__ __align__(16) float sh_acc[NWARP][GG][DD];   // 8 KB
    __shared__ float sh_l[NWARP][GG];

    // softmax in log2 domain; fold scale*log2e into Q.
    // Lane owns dims {c*64 + sub*4 .. +3} for c in {0,1}
    const float scale = 0.08838834764831845f * 1.4426950408889634f;
    float4 qv[GG][2];
#pragma unroll
    for (int g = 0; g < GG; g++)
#pragma unroll
        for (int c = 0; c < 2; c++) {
            float4 q = *(const float4*)(xq + ((size_t)b * HQ + h * GG + g) * DD
                                        + c * 64 + sub * 4);
            q.x *= scale; q.y *= scale; q.z *= scale; q.w *= scale;
            qv[g][c] = q;
        }

    float  l[GG];
    float4 acc[GG][2];
#pragma unroll
    for (int g = 0; g < GG; g++) {
        l[g] = 0.f;
        acc[g][0] = make_float4(0.f,0.f,0.f,0.f);
        acc[g][1] = make_float4(0.f,0.f,0.f,0.f);
    }

    const int    tbase = b * SS;
    const size_t qkvo  = ((size_t)b * HKV + h) * DD;
    const size_t rowsz = (size_t)(2 * HKV * DD);
    const size_t koff  = (size_t)h * DD;
    const size_t voff  = (size_t)(HKV + h) * DD;

    const int tmax  = nt - 1;
    const int niter = (nt + SLOTS - 1) / SLOTS;

    // depth-2 rotated prefetch: stage st holds iteration (i) K/V; nr[st] holds
    // the row index for iteration (i+2)'s token.
    float4 bk[2][2], bv[2][2];
    int    nr[2];

#pragma unroll
    for (int st = 0; st < 2; st++) {
        int t = min(st * SLOTS + myslot, tmax);
        int r = __ldg(table + tbase + split + NSPLIT * t);
        const float* kp = (r == cur) ? xk + qkvo : kv + (size_t)r * rowsz + koff;
        const float* vp = (r == cur) ? xv + qkvo : kv + (size_t)r * rowsz + voff;
        bk[st][0] = *(const float4*)(kp + sub * 4);
        bk[st][1] = *(const float4*)(kp + sub * 4 + 64);
        bv[st][0] = *(const float4*)(vp + sub * 4);
        bv[st][1] = *(const float4*)(vp + sub * 4 + 64);
    }
#pragma unroll
    for (int st = 0; st < 2; st++)
        nr[st] = __ldg(table + tbase + split
                       + NSPLIT * min((2 + st) * SLOTS + myslot, tmax));

    for (int i = 0; i < niter; i += 2) {
#pragma unroll
        for (int st = 0; st < 2; st++) {
            const int it = i + st;
            if (st == 1 && it >= niter) break;

            // grab current stage
            float4 k0 = bk[st][0], k1 = bk[st][1];
            float4 v0 = bv[st][0], v1 = bv[st][1];

            // refill stage with iteration (it+2); row prefetched, clamp-safe
            {
                int r = nr[st];
                const float* kp = (r == cur) ? xk + qkvo : kv + (size_t)r * rowsz + koff;
                const float* vp = (r == cur) ? xv + qkvo : kv + (size_t)r * rowsz + voff;
                bk[st][0] = *(const float4*)(kp + sub * 4);
                bk[st][1] = *(const float4*)(kp + sub * 4 + 64);
                bv[st][0] = *(const float4*)(vp + sub * 4);
                bv[st][1] = *(const float4*)(vp + sub * 4 + 64);
                nr[st] = __ldg(table + tbase + split
                               + NSPLIT * min((it + 4) * SLOTS + myslot, tmax));
            }

            // dot for 4 heads over this lane's 8 dims
            float x[GG];
#pragma unroll
            for (int g = 0; g < GG; g++)
                x[g] = dot4(k0, qv[g][0]) + dot4(k1, qv[g][1]);

            // 16-lane group reduce: 4 levels, all lanes end with the full sum
#pragma unroll
            for (int g = 0; g < GG; g++) x[g] += __shfl_xor_sync(0xffffffffu, x[g], 1);
#pragma unroll
            for (int g = 0; g < GG; g++) x[g] += __shfl_xor_sync(0xffffffffu, x[g], 2);
#pragma unroll
            for (int g = 0; g < GG; g++) x[g] += __shfl_xor_sync(0xffffffffu, x[g], 4);
#pragma unroll
            for (int g = 0; g < GG; g++) x[g] += __shfl_xor_sync(0xffffffffu, x[g], 8);

            const bool valid = (it * SLOTS + myslot) < nt;
#pragma unroll
            for (int g = 0; g < GG; g++) {
                float p = valid ? exp2f(x[g]) : 0.f;
                l[g] += p;
                acc[g][0].x += p * v0.x; acc[g][0].y += p * v0.y;
                acc[g][0].z += p * v0.z; acc[g][0].w += p * v0.w;
                acc[g][1].x += p * v1.x; acc[g][1].y += p * v1.y;
                acc[g][1].z += p * v1.z; acc[g][1].w += p * v1.w;
            }
        }
    }

    // merge the two 16-lane groups (different tokens, same dims): xor 16
#pragma unroll
    for (int g = 0; g < GG; g++) {
#pragma unroll
        for (int c = 0; c < 2; c++) {
            acc[g][c].x += __shfl_xor_sync(0xffffffffu, acc[g][c].x, 16);
            acc[g][c].y += __shfl_xor_sync(0xffffffffu, acc[g][c].y, 16);
            acc[g][c].z += __shfl_xor_sync(0xffffffffu, acc[g][c].z, 16);
            acc[g][c].w += __shfl_xor_sync(0xffffffffu, acc[g][c].w, 16);
        }
        l[g] += __shfl_xor_sync(0xffffffffu, l[g], 16);
    }

    // lanes 0..15 write this warp's partial to smem
    if (grp == 0) {
#pragma unroll
        for (int g = 0; g < GG; g++) {
#pragma unroll
            for (int c = 0; c < 2; c++)
                *(float4*)&sh_acc[wid][g][c * 64 + sub * 4] = acc[g][c];
            if (sub == 0) sh_l[wid][g] = l[g];
        }
    }
    __syncthreads();

    // cross-warp merge + write partials
    for (int idx = tid; idx < GG * DD; idx += NTHR) {
        const int g = idx >> 7;
        const int d = idx & (DD - 1);
        float A = 0.f;
#pragma unroll
        for (int w = 0; w < NWARP; w++) A += sh_acc[w][g][d];
        const size_t po = (size_t)split * BB * HQ + (size_t)b * HQ + h * GG + g;
        g_pacc[po * DD + d] = A;
        if (d == 0) {
            float L = 0.f;
#pragma unroll
            for (int w = 0; w < NWARP; w++) L += sh_l[w][g];
            g_pl[po] = L;
        }
    }
}

// 256 blocks x 256 threads, 4 (b,qh) per block, float2 per thread:
// 32 independent loads in flight per thread, ~4x fewer blocks than before.
__global__ __launch_bounds__(256) void attn_combine(float* __restrict__ out)
{
    const int bq = blockIdx.x * 4 + (threadIdx.x >> 6);  // 4 heads per block
    const int d2 = (threadIdx.x & 63) * 2;               // even dim pair

    float L = 0.f, A0 = 0.f, A1 = 0.f;
#pragma unroll
    for (int i = 0; i < NSPLIT; i++) {
        const size_t po = (size_t)i * BB * HQ + bq;
        L += g_pl[po];
        float2 a = *(const float2*)&g_pacc[po * DD + d2];
        A0 += a.x; A1 += a.y;
    }
    const float inv = 1.f / L;
    out[(size_t)bq * DD + d2]     = A0 * inv;
    out[(size_t)bq * DD + d2 + 1] = A1 * inv;
}

extern "C" void kernel_launch(void* const* d_in, const int* in_sizes, int n_in,
                              void* d_out, int out_size)
{
    const float* xq      = (const float*)d_in[0];
    const float* xk      = (const float*)d_in[1];
    const float* xv      = (const float*)d_in[2];
    const float* kv      = (const float*)d_in[3];
    const int*   cur_sel = (const int*)d_in[4];
    const int*   table   = (const int*)d_in[5];
    const int*   seqlens = (const int*)d_in[6];
    float*       out     = (float*)d_out;

    sort_batches<<<1, BB>>>(seqlens);
    dim3 grid(NSPLIT, HKV, BB);
    attn_partial<<<grid, NTHR>>>(xq, xk, xv, kv, cur_sel, table, seqlens);
    attn_combine<<<BB * HQ / 4, 256>>>(out);
}

// round 15
// speedup vs baseline: 1.1122x; 1.0102x over previous
#include <cuda_runtime.h>

// Problem constants
#define BB     32
#define HQ     32
#define HKV    8
#define DD     128
#define SS     4096
#define GG     4          // HQ / HKV
#define NSPLIT 16         // interleaved: split i takes tokens s ≡ i (mod 16)
#define NWARP  4
#define NTHR   128
#define SLOTS  (NWARP * 2)   // 8 tokens per CTA iteration (2 per warp: 16-lane groups)

// Split-KV partial scratch (allocation-free: __device__ globals)
__device__ float g_pacc[(size_t)NSPLIT * BB * HQ * DD];   // 8.4 MB
__device__ float g_pl[NSPLIT * BB * HQ];

__device__ __forceinline__ float dot4(float4 a, float4 b) {
    return a.x*b.x + a.y*b.y + a.z*b.z + a.w*b.w;
}

__global__ __launch_bounds__(NTHR, 4) void attn_partial(
    const float* __restrict__ xq, const float* __restrict__ xk,
    const float* __restrict__ xv, const float* __restrict__ kv,
    const int* __restrict__ cur_sel, const int* __restrict__ table,
    const int* __restrict__ seqlens)
{
    const int split = blockIdx.x;
    const int h     = blockIdx.y;
    const int b     = blockIdx.z;

    const int seq_len = seqlens[b];
    // Interleaved split: tokens s = split + NSPLIT * t, t in [0, nt).
    // seq_len >= 1024 > NSPLIT, so nt >= 64: every split is always active.
    const int nt  = (seq_len - split + NSPLIT - 1) / NSPLIT;
    const int cur = cur_sel[b];

    const int tid  = threadIdx.x;
    const int wid  = tid >> 5;
    const int lane = tid & 31;
    const int sub  = lane & 15;          // position within 16-lane group
    const int grp  = lane >> 4;          // 0 or 1: which token this half-warp owns
    const int myslot = wid * 2 + grp;    // 0..7 token slot within CTA iteration

    __shared__ __align__(16) float sh_acc[NWARP][GG][DD];   // 8 KB
    __shared__ float sh_l[NWARP][GG];

    // softmax in log2 domain; fold scale*log2e into Q.
    // Lane owns dims {c*64 + sub*4 .. +3} for c in {0,1}
    const float scale = 0.08838834764831845f * 1.4426950408889634f;
    float4 qv[GG][2];
#pragma unroll
    for (int g = 0; g < GG; g++)
#pragma unroll
        for (int c = 0; c < 2; c++) {
            float4 q = *(const float4*)(xq + ((size_t)b * HQ + h * GG + g) * DD
                                        + c * 64 + sub * 4);
            q.x *= scale; q.y *= scale; q.z *= scale; q.w *= scale;
            qv[g][c] = q;
        }

    float  l[GG];
    float4 acc[GG][2];
#pragma unroll
    for (int g = 0; g < GG; g++) {
        l[g] = 0.f;
        acc[g][0] = make_float4(0.f,0.f,0.f,0.f);
        acc[g][1] = make_float4(0.f,0.f,0.f,0.f);
    }

    const int    tbase = b * SS;
    const size_t qkvo  = ((size_t)b * HKV + h) * DD;
    const size_t rowsz = (size_t)(2 * HKV * DD);
    const size_t koff  = (size_t)h * DD;
    const size_t voff  = (size_t)(HKV + h) * DD;

    const int tmax  = nt - 1;
    const int niter = (nt + SLOTS - 1) / SLOTS;

    // depth-2 rotated prefetch: stage st holds iteration (i) K/V; nr[st] holds
    // the row index for iteration (i+2)'s token.
    float4 bk[2][2], bv[2][2];
    int    nr[2];

#pragma unroll
    for (int st = 0; st < 2; st++) {
        int t = min(st * SLOTS + myslot, tmax);
        int r = __ldg(table + tbase + split + NSPLIT * t);
        const float* kp = (r == cur) ? xk + qkvo : kv + (size_t)r * rowsz + koff;
        const float* vp = (r == cur) ? xv + qkvo : kv + (size_t)r * rowsz + voff;
        bk[st][0] = *(const float4*)(kp + sub * 4);
        bk[st][1] = *(const float4*)(kp + sub * 4 + 64);
        bv[st][0] = *(const float4*)(vp + sub * 4);
        bv[st][1] = *(const float4*)(vp + sub * 4 + 64);
    }
#pragma unroll
    for (int st = 0; st < 2; st++)
        nr[st] = __ldg(table + tbase + split
                       + NSPLIT * min((2 + st) * SLOTS + myslot, tmax));

    for (int i = 0; i < niter; i += 2) {
#pragma unroll
        for (int st = 0; st < 2; st++) {
            const int it = i + st;
            if (st == 1 && it >= niter) break;

            // grab current stage
            float4 k0 = bk[st][0], k1 = bk[st][1];
            float4 v0 = bv[st][0], v1 = bv[st][1];

            // refill stage with iteration (it+2); row prefetched, clamp-safe
            {
                int r = nr[st];
                const float* kp = (r == cur) ? xk + qkvo : kv + (size_t)r * rowsz + koff;
                const float* vp = (r == cur) ? xv + qkvo : kv + (size_t)r * rowsz + voff;
                bk[st][0] = *(const float4*)(kp + sub * 4);
                bk[st][1] = *(const float4*)(kp + sub * 4 + 64);
                bv[st][0] = *(const float4*)(vp + sub * 4);
                bv[st][1] = *(const float4*)(vp + sub * 4 + 64);
                nr[st] = __ldg(table + tbase + split
                               + NSPLIT * min((it + 4) * SLOTS + myslot, tmax));
            }

            // dot for 4 heads over this lane's 8 dims
            float x[GG];
#pragma unroll
            for (int g = 0; g < GG; g++)
                x[g] = dot4(k0, qv[g][0]) + dot4(k1, qv[g][1]);

            // 16-lane group reduce: 4 levels, all lanes end with the full sum
#pragma unroll
            for (int g = 0; g < GG; g++) x[g] += __shfl_xor_sync(0xffffffffu, x[g], 1);
#pragma unroll
            for (int g = 0; g < GG; g++) x[g] += __shfl_xor_sync(0xffffffffu, x[g], 2);
#pragma unroll
            for (int g = 0; g < GG; g++) x[g] += __shfl_xor_sync(0xffffffffu, x[g], 4);
#pragma unroll
            for (int g = 0; g < GG; g++) x[g] += __shfl_xor_sync(0xffffffffu, x[g], 8);

            const bool valid = (it * SLOTS + myslot) < nt;
#pragma unroll
            for (int g = 0; g < GG; g++) {
                float p = valid ? exp2f(x[g]) : 0.f;
                l[g] += p;
                acc[g][0].x += p * v0.x; acc[g][0].y += p * v0.y;
                acc[g][0].z += p * v0.z; acc[g][0].w += p * v0.w;
                acc[g][1].x += p * v1.x; acc[g][1].y += p * v1.y;
                acc[g][1].z += p * v1.z; acc[g][1].w += p * v1.w;
            }
        }
    }

    // merge the two 16-lane groups (different tokens, same dims): xor 16
#pragma unroll
    for (int g = 0; g < GG; g++) {
#pragma unroll
        for (int c = 0; c < 2; c++) {
            acc[g][c].x += __shfl_xor_sync(0xffffffffu, acc[g][c].x, 16);
            acc[g][c].y += __shfl_xor_sync(0xffffffffu, acc[g][c].y, 16);
            acc[g][c].z += __shfl_xor_sync(0xffffffffu, acc[g][c].z, 16);
            acc[g][c].w += __shfl_xor_sync(0xffffffffu, acc[g][c].w, 16);
        }
        l[g] += __shfl_xor_sync(0xffffffffu, l[g], 16);
    }

    // lanes 0..15 write this warp's partial to smem
    if (grp == 0) {
#pragma unroll
        for (int g = 0; g < GG; g++) {
#pragma unroll
            for (int c = 0; c < 2; c++)
                *(float4*)&sh_acc[wid][g][c * 64 + sub * 4] = acc[g][c];
            if (sub == 0) sh_l[wid][g] = l[g];
        }
    }
    __syncthreads();

    // cross-warp merge + write partials
    for (int idx = tid; idx < GG * DD; idx += NTHR) {
        const int g = idx >> 7;
        const int d = idx & (DD - 1);
        float A = 0.f;
#pragma unroll
        for (int w = 0; w < NWARP; w++) A += sh_acc[w][g][d];
        const size_t po = (size_t)split * BB * HQ + (size_t)b * HQ + h * GG + g;
        g_pacc[po * DD + d] = A;
        if (d == 0) {
            float L = 0.f;
#pragma unroll
            for (int w = 0; w < NWARP; w++) L += sh_l[w][g];
            g_pl[po] = L;
        }
    }
}

// 256 blocks x 256 threads, 4 (b,qh) per block, float2 per thread:
// 32 independent loads in flight per thread.
__global__ __launch_bounds__(256) void attn_combine(float* __restrict__ out)
{
    const int bq = blockIdx.x * 4 + (threadIdx.x >> 6);  // 4 heads per block
    const int d2 = (threadIdx.x & 63) * 2;               // even dim pair

    float L = 0.f, A0 = 0.f, A1 = 0.f;
#pragma unroll
    for (int i = 0; i < NSPLIT; i++) {
        const size_t po = (size_t)i * BB * HQ + bq;
        L += g_pl[po];
        float2 a = *(const float2*)&g_pacc[po * DD + d2];
        A0 += a.x; A1 += a.y;
    }
    const float inv = 1.f / L;
    out[(size_t)bq * DD + d2]     = A0 * inv;
    out[(size_t)bq * DD + d2 + 1] = A1 * inv;
}

extern "C" void kernel_launch(void* const* d_in, const int* in_sizes, int n_in,
                              void* d_out, int out_size)
{
    const float* xq      = (const float*)d_in[0];
    const float* xk      = (const float*)d_in[1];
    const float* xv      = (const float*)d_in[2];
    const float* kv      = (const float*)d_in[3];
    const int*   cur_sel = (const int*)d_in[4];
    const int*   table   = (const int*)d_in[5];
    const int*   seqlens = (const int*)d_in[6];
    float*       out     = (float*)d_out;

    dim3 grid(NSPLIT, HKV, BB);
    attn_partial<<<grid, NTHR>>>(xq, xk, xv, kv, cur_sel, table, seqlens);
    attn_combine<<<BB * HQ / 4, 256>>>(out);
}

// round 17
// speedup vs baseline: 1.1761x; 1.0575x over previous
#include <cuda_runtime.h>

// Problem constants
#define BB     32
#define HQ     32
#define HKV    8
#define DD     128
#define SS     4096
#define GG     4          // HQ / HKV
#define NSPLIT 16         // interleaved: split i takes tokens s ≡ i (mod 16)
#define NWARP  4
#define NTHR   128
#define SLOTS  (NWARP * 2)   // 8 tokens per CTA iteration (2 per warp: 16-lane groups)

// Output-shaped accumulators. Zero-initialized at module load; attn_finalize
// re-zeroes them after each use so every graph replay starts clean.
__device__ float g_acc[(size_t)BB * HQ * DD];   // 2 MB
__device__ float g_l[BB * HQ];

__device__ __forceinline__ float dot4(float4 a, float4 b) {
    return a.x*b.x + a.y*b.y + a.z*b.z + a.w*b.w;
}

__global__ __launch_bounds__(NTHR, 4) void attn_partial(
    const float* __restrict__ xq, const float* __restrict__ xk,
    const float* __restrict__ xv, const float* __restrict__ kv,
    const int* __restrict__ cur_sel, const int* __restrict__ table,
    const int* __restrict__ seqlens)
{
    const int split = blockIdx.x;
    const int h     = blockIdx.y;
    const int b     = blockIdx.z;

    const int seq_len = seqlens[b];
    // Interleaved split: tokens s = split + NSPLIT * t, t in [0, nt).
    // seq_len >= 1024 > NSPLIT, so nt >= 64: every split is always active.
    const int nt  = (seq_len - split + NSPLIT - 1) / NSPLIT;
    const int cur = cur_sel[b];

    const int tid  = threadIdx.x;
    const int wid  = tid >> 5;
    const int lane = tid & 31;
    const int sub  = lane & 15;          // position within 16-lane group
    const int grp  = lane >> 4;          // 0 or 1: which token this half-warp owns
    const int myslot = wid * 2 + grp;    // 0..7 token slot within CTA iteration

    __shared__ __align__(16) float sh_acc[NWARP][GG][DD];   // 8 KB
    __shared__ float sh_l[NWARP][GG];

    // softmax in log2 domain; fold scale*log2e into Q.
    // Lane owns dims {c*64 + sub*4 .. +3} for c in {0,1}
    const float scale = 0.08838834764831845f * 1.4426950408889634f;
    float4 qv[GG][2];
#pragma unroll
    for (int g = 0; g < GG; g++)
#pragma unroll
        for (int c = 0; c < 2; c++) {
            float4 q = *(const float4*)(xq + ((size_t)b * HQ + h * GG + g) * DD
                                        + c * 64 + sub * 4);
            q.x *= scale; q.y *= scale; q.z *= scale; q.w *= scale;
            qv[g][c] = q;
        }

    float  l[GG];
    float4 acc[GG][2];
#pragma unroll
    for (int g = 0; g < GG; g++) {
        l[g] = 0.f;
        acc[g][0] = make_float4(0.f,0.f,0.f,0.f);
        acc[g][1] = make_float4(0.f,0.f,0.f,0.f);
    }

    const int    tbase = b * SS;
    const size_t qkvo  = ((size_t)b * HKV + h) * DD;
    const size_t rowsz = (size_t)(2 * HKV * DD);
    const size_t koff  = (size_t)h * DD;
    const size_t voff  = (size_t)(HKV + h) * DD;

    const int tmax  = nt - 1;
    const int niter = (nt + SLOTS - 1) / SLOTS;

    // depth-2 rotated prefetch: stage st holds iteration (i) K/V; nr[st] holds
    // the row index for iteration (i+2)'s token.
    float4 bk[2][2], bv[2][2];
    int    nr[2];

#pragma unroll
    for (int st = 0; st < 2; st++) {
        int t = min(st * SLOTS + myslot, tmax);
        int r = __ldg(table + tbase + split + NSPLIT * t);
        const float* kp = (r == cur) ? xk + qkvo : kv + (size_t)r * rowsz + koff;
        const float* vp = (r == cur) ? xv + qkvo : kv + (size_t)r * rowsz + voff;
        bk[st][0] = *(const float4*)(kp + sub * 4);
        bk[st][1] = *(const float4*)(kp + sub * 4 + 64);
        bv[st][0] = *(const float4*)(vp + sub * 4);
        bv[st][1] = *(const float4*)(vp + sub * 4 + 64);
    }
#pragma unroll
    for (int st = 0; st < 2; st++)
        nr[st] = __ldg(table + tbase + split
                       + NSPLIT * min((2 + st) * SLOTS + myslot, tmax));

    for (int i = 0; i < niter; i += 2) {
#pragma unroll
        for (int st = 0; st < 2; st++) {
            const int it = i + st;
            if (st == 1 && it >= niter) break;

            // grab current stage
            float4 k0 = bk[st][0], k1 = bk[st][1];
            float4 v0 = bv[st][0], v1 = bv[st][1];

            // refill stage with iteration (it+2); row prefetched, clamp-safe
            {
                int r = nr[st];
                const float* kp = (r == cur) ? xk + qkvo : kv + (size_t)r * rowsz + koff;
                const float* vp = (r == cur) ? xv + qkvo : kv + (size_t)r * rowsz + voff;
                bk[st][0] = *(const float4*)(kp + sub * 4);
                bk[st][1] = *(const float4*)(kp + sub * 4 + 64);
                bv[st][0] = *(const float4*)(vp + sub * 4);
                bv[st][1] = *(const float4*)(vp + sub * 4 + 64);
                nr[st] = __ldg(table + tbase + split
                               + NSPLIT * min((it + 4) * SLOTS + myslot, tmax));
            }

            // dot for 4 heads over this lane's 8 dims
            float x[GG];
#pragma unroll
            for (int g = 0; g < GG; g++)
                x[g] = dot4(k0, qv[g][0]) + dot4(k1, qv[g][1]);

            // 16-lane group reduce: 4 levels, all lanes end with the full sum
#pragma unroll
            for (int g = 0; g < GG; g++) x[g] += __shfl_xor_sync(0xffffffffu, x[g], 1);
#pragma unroll
            for (int g = 0; g < GG; g++) x[g] += __shfl_xor_sync(0xffffffffu, x[g], 2);
#pragma unroll
            for (int g = 0; g < GG; g++) x[g] += __shfl_xor_sync(0xffffffffu, x[g], 4);
#pragma unroll
            for (int g = 0; g < GG; g++) x[g] += __shfl_xor_sync(0xffffffffu, x[g], 8);

            const bool valid = (it * SLOTS + myslot) < nt;
#pragma unroll
            for (int g = 0; g < GG; g++) {
                float p = valid ? exp2f(x[g]) : 0.f;
                l[g] += p;
                acc[g][0].x += p * v0.x; acc[g][0].y += p * v0.y;
                acc[g][0].z += p * v0.z; acc[g][0].w += p * v0.w;
                acc[g][1].x += p * v1.x; acc[g][1].y += p * v1.y;
                acc[g][1].z += p * v1.z; acc[g][1].w += p * v1.w;
            }
        }
    }

    // merge the two 16-lane groups (different tokens, same dims): xor 16
#pragma unroll
    for (int g = 0; g < GG; g++) {
#pragma unroll
        for (int c = 0; c < 2; c++) {
            acc[g][c].x += __shfl_xor_sync(0xffffffffu, acc[g][c].x, 16);
            acc[g][c].y += __shfl_xor_sync(0xffffffffu, acc[g][c].y, 16);
            acc[g][c].z += __shfl_xor_sync(0xffffffffu, acc[g][c].z, 16);
            acc[g][c].w += __shfl_xor_sync(0xffffffffu, acc[g][c].w, 16);
        }
        l[g] += __shfl_xor_sync(0xffffffffu, l[g], 16);
    }

    // lanes 0..15 write this warp's partial to smem
    if (grp == 0) {
#pragma unroll
        for (int g = 0; g < GG; g++) {
#pragma unroll
            for (int c = 0; c < 2; c++)
                *(float4*)&sh_acc[wid][g][c * 64 + sub * 4] = acc[g][c];
            if (sub == 0) sh_l[wid][g] = l[g];
        }
    }
    __syncthreads();

    // cross-warp merge + atomic flush straight into the output-shaped
    // accumulator (REDG no-return, spread addresses): no scratch round-trip.
    for (int idx = tid; idx < GG * DD; idx += NTHR) {
        const int g = idx >> 7;
        const int d = idx & (DD - 1);
        float A = 0.f;
#pragma unroll
        for (int w = 0; w < NWARP; w++) A += sh_acc[w][g][d];
        atomicAdd(&g_acc[((size_t)b * HQ + h * GG + g) * DD + d], A);
        if (d == 0) {
            float L = 0.f;
#pragma unroll
            for (int w = 0; w < NWARP; w++) L += sh_l[w][g];
            atomicAdd(&g_l[b * HQ + h * GG + g], L);
        }
    }
}

// Divide by the normalizer and self-zero the accumulators for the next replay.
__global__ __launch_bounds__(DD) void attn_finalize(float* __restrict__ out)
{
    const int bq = blockIdx.x;      // b*HQ + qh
    const int d  = threadIdx.x;
    const size_t o = (size_t)bq * DD + d;

    const float A = g_acc[o];
    const float L = g_l[bq];        // broadcast read by all 128 threads
    __syncthreads();                // everyone has read before we zero

    out[o] = A / L;
    g_acc[o] = 0.f;
    if (d == 0) g_l[bq] = 0.f;
}

extern "C" void kernel_launch(void* const* d_in, const int* in_sizes, int n_in,
                              void* d_out, int out_size)
{
    const float* xq      = (const float*)d_in[0];
    const float* xk      = (const float*)d_in[1];
    const float* xv      = (const float*)d_in[2];
    const float* kv      = (const float*)d_in[3];
    const int*   cur_sel = (const int*)d_in[4];
    const int*   table   = (const int*)d_in[5];
    const int*   seqlens = (const int*)d_in[6];
    float*       out     = (float*)d_out;

    dim3 grid(NSPLIT, HKV, BB);
    attn_partial<<<grid, NTHR>>>(xq, xk, xv, kv, cur_sel, table, seqlens);
    attn_finalize<<<BB * HQ, DD>>>(out);
}